// round 6
// baseline (speedup 1.0000x reference)
#include <cuda_runtime.h>
#include <cstdint>

// LearnableFiltration via mma.sync tf32 (sm_103 family target: no tcgen05).
// out[b,i,j] = softplus( relu( relu(H1) @ W2 + b2 ) @ W3 + b3 )
// H1[j,h] = wi*W1[0,h] + wj*W1[1,h] + d_ij*W1[2,h] + b1[h];  B=4,N=1024,H=32.
//
// R6 = R5 body unchanged; GRID 444 -> 592 (4 blocks/SM, occupancy was
// grid-limited: regs=124 so 4 blocks fit without any cap).

#define NB    4
#define NN    1024
#define NH    32
#define TPB   128                        // 4 warps / block
#define GRID  592                        // 4 blocks/SM * 148 SMs
#define NWT   (NB * NN * (NN / 16))      // 262144 warp-tiles of 16 j's

static __device__ __forceinline__ uint32_t to_tf32(float x) {
    uint32_t r;
    asm("cvt.rna.tf32.f32 %0, %1;" : "=r"(r) : "f"(x));
    return r;
}

// D += A*B (in-place accumulate)
static __device__ __forceinline__ void mma_acc(float* d, const uint32_t* a,
                                               const uint32_t* b) {
    asm volatile(
        "mma.sync.aligned.m16n8k8.row.col.f32.tf32.tf32.f32 "
        "{%0,%1,%2,%3}, {%4,%5,%6,%7}, {%8,%9}, {%0,%1,%2,%3};"
        : "+f"(d[0]), "+f"(d[1]), "+f"(d[2]), "+f"(d[3])
        : "r"(a[0]), "r"(a[1]), "r"(a[2]), "r"(a[3]), "r"(b[0]), "r"(b[1]));
}
// D = A*B + {c0,c1,c0,c1}  (bias init: writes D fresh)
static __device__ __forceinline__ void mma_bias(float* d, const uint32_t* a,
                                                const uint32_t* b,
                                                float c0, float c1) {
    asm volatile(
        "mma.sync.aligned.m16n8k8.row.col.f32.tf32.tf32.f32 "
        "{%0,%1,%2,%3}, {%4,%5,%6,%7}, {%8,%9}, {%10,%11,%10,%11};"
        : "=f"(d[0]), "=f"(d[1]), "=f"(d[2]), "=f"(d[3])
        : "r"(a[0]), "r"(a[1]), "r"(a[2]), "r"(a[3]), "r"(b[0]), "r"(b[1]),
          "f"(c0), "f"(c1));
}

// softplus(x) = max(x,0) + ln2 * lg2(1 + 2^(-|x|*log2e)), MUFU approx
static __device__ __forceinline__ float softplus_fast(float x) {
    float t, l;
    const float nax = -fabsf(x) * 1.442695041f;
    asm("ex2.approx.f32 %0, %1;" : "=f"(t) : "f"(nax));
    asm("lg2.approx.f32 %0, %1;" : "=f"(l) : "f"(t + 1.0f));
    return fmaxf(x, 0.0f) + 0.693147181f * l;
}

__global__ void __launch_bounds__(TPB)
lf_mma6_kernel(const float* __restrict__ weights,
               const float* __restrict__ distances,
               const float* __restrict__ W1,
               const float* __restrict__ b1,
               const float* __restrict__ W2,
               const float* __restrict__ b2,
               const float* __restrict__ W3,
               const float* __restrict__ b3,
               float* __restrict__ out)
{
    __shared__ float  sW[NB * NN];    // all weights (16 KB)
    __shared__ float4 sW1[NH];        // {W1[0,h], W1[1,h], W1[2,h], b1[h]}
    __shared__ float2 sBW[NH];        // {b2[k], W3[k]}
    __shared__ float  sW2[NH * NH];   // W2[h][n] row-major

    const int tid  = threadIdx.x;
    const int wid  = tid >> 5;
    const int lane = tid & 31;
    const int q    = lane & 3;        // k / col position in quad
    const int g    = lane >> 2;       // row position

    for (int x = tid; x < (NB * NN) / 4; x += TPB)
        ((float4*)sW)[x] = ((const float4*)weights)[x];
    for (int x = tid; x < (NH * NH) / 4; x += TPB)
        ((float4*)sW2)[x] = ((const float4*)W2)[x];
    if (tid < NH) {
        sW1[tid] = make_float4(W1[tid], W1[NH + tid], W1[2 * NH + tid], b1[tid]);
        sBW[tid] = make_float2(b2[tid], W3[tid]);
    }
    __syncthreads();

    // ---- loop-invariant register state ----
    uint32_t bf[4][4][2];             // W2^T fragments (tf32)
#pragma unroll
    for (int kt = 0; kt < 4; kt++)
#pragma unroll
        for (int nt = 0; nt < 4; nt++) {
            bf[kt][nt][0] = to_tf32(sW2[(kt * 8 + q) * NH + nt * 8 + g]);
            bf[kt][nt][1] = to_tf32(sW2[(kt * 8 + q + 4) * NH + nt * 8 + g]);
        }
    float4 w1c[8];                    // W1 cols h = q + {0,4} + 8kt
#pragma unroll
    for (int kt = 0; kt < 4; kt++) {
        w1c[2 * kt]     = sW1[8 * kt + q];
        w1c[2 * kt + 1] = sW1[8 * kt + q + 4];
    }
    float2 bw[8];                     // {b2, W3} at n = 8nt + 2q + {0,1}
#pragma unroll
    for (int nt = 0; nt < 4; nt++) {
        bw[2 * nt]     = sBW[8 * nt + 2 * q];
        bw[2 * nt + 1] = sBW[8 * nt + 2 * q + 1];
    }
    const float b3v = b3[0];

    const int gw     = blockIdx.x * 4 + wid;
    const int stride = GRID * 4;

    // prefetch first tile's distances (flat elem offset = t*16 + g)
    float d0 = 0.f, d1 = 0.f;
    if (gw < NWT) {
        const unsigned off = ((unsigned)gw << 4) + g;
        d0 = __ldcs(distances + off);
        d1 = __ldcs(distances + off + 8);
    }

    for (int t = gw; t < NWT; t += stride) {
        const unsigned off = ((unsigned)t << 4) + g;

        const float wi = sW[t >> 6];
        const unsigned jbase = ((unsigned)(t >> 16) << 10) + ((t & 63) << 4) + g;
        const float wj0 = sW[jbase];
        const float wj1 = sW[jbase + 8];

        // ---- A fragments: rows {g,g+8}, cols q+{0,4}+8kt; raw-bit tf32 ----
        uint32_t af[4][4];
#pragma unroll
        for (int kt = 0; kt < 4; kt++) {
            const float4 cA = w1c[2 * kt];
            const float4 cB = w1c[2 * kt + 1];
            const float aiA = fmaf(cA.x, wi, cA.w);
            const float aiB = fmaf(cB.x, wi, cB.w);
            af[kt][0] = __float_as_uint(fmaxf(fmaf(cA.z, d0, fmaf(cA.y, wj0, aiA)), 0.f));
            af[kt][1] = __float_as_uint(fmaxf(fmaf(cA.z, d1, fmaf(cA.y, wj1, aiA)), 0.f));
            af[kt][2] = __float_as_uint(fmaxf(fmaf(cB.z, d0, fmaf(cB.y, wj0, aiB)), 0.f));
            af[kt][3] = __float_as_uint(fmaxf(fmaf(cB.z, d1, fmaf(cB.y, wj1, aiB)), 0.f));
        }

        // prefetch next tile (hide LDG under MMA + epilogue)
        const int tn = t + stride;
        float d0n = 0.f, d1n = 0.f;
        if (tn < NWT) {
            const unsigned offn = ((unsigned)tn << 4) + g;
            d0n = __ldcs(distances + offn);
            d1n = __ldcs(distances + offn + 8);
        }

        // ---- 16 HMMAs; first k-step carries b2 bias as C ----
        float acc[4][4];
#pragma unroll
        for (int nt = 0; nt < 4; nt++)
            mma_bias(acc[nt], af[0], bf[0][nt], bw[2 * nt].x, bw[2 * nt + 1].x);
#pragma unroll
        for (int kt = 1; kt < 4; kt++)
#pragma unroll
            for (int nt = 0; nt < 4; nt++)
                mma_acc(acc[nt], af[kt], bf[kt][nt]);

        // ---- epilogue: relu . W3, quad reduce, softplus ----
        float s0 = 0.f, s1 = 0.f;
#pragma unroll
        for (int nt = 0; nt < 4; nt++) {
            const float w30 = bw[2 * nt].y;
            const float w31 = bw[2 * nt + 1].y;
            s0 = fmaf(fmaxf(acc[nt][0], 0.f), w30, s0);
            s0 = fmaf(fmaxf(acc[nt][1], 0.f), w31, s0);
            s1 = fmaf(fmaxf(acc[nt][2], 0.f), w30, s1);
            s1 = fmaf(fmaxf(acc[nt][3], 0.f), w31, s1);
        }
        s0 += __shfl_xor_sync(0xffffffffu, s0, 1);
        s0 += __shfl_xor_sync(0xffffffffu, s0, 2);
        s1 += __shfl_xor_sync(0xffffffffu, s1, 1);
        s1 += __shfl_xor_sync(0xffffffffu, s1, 2);

        if (q == 0) {
            __stcs(out + off,     softplus_fast(s0 + b3v));
            __stcs(out + off + 8, softplus_fast(s1 + b3v));
        }

        d0 = d0n;
        d1 = d1n;
    }
}

extern "C" void kernel_launch(void* const* d_in, const int* in_sizes, int n_in,
                              void* d_out, int out_size)
{
    const float* weights   = (const float*)d_in[0];
    const float* distances = (const float*)d_in[1];
    const float* W1        = (const float*)d_in[2];
    const float* b1        = (const float*)d_in[3];
    const float* W2        = (const float*)d_in[4];
    const float* b2        = (const float*)d_in[5];
    const float* W3        = (const float*)d_in[6];
    const float* b3        = (const float*)d_in[7];
    float* out             = (float*)d_out;

    lf_mma6_kernel<<<GRID, TPB>>>(weights, distances, W1, b1, W2, b2, W3, b3, out);
}

// round 7
// speedup vs baseline: 1.1245x; 1.1245x over previous
#include <cuda_runtime.h>
#include <cstdint>

// LearnableFiltration via mma.sync tf32 (sm_103 family target: no tcgen05).
// out[b,i,j] = softplus( relu( relu(H1) @ W2 + b2 ) @ W3 + b3 )
// H1[j,h] = wi*W1[0,h] + wj*W1[1,h] + d_ij*W1[2,h] + b1[h];  B=4,N=1024,H=32.
//
// R7: 32-row warp tiles = two independent 16x32 MMA tiles per iteration,
// interleaved at the kt level for 2x independent dependency chains;
// bookkeeping + ai[h] precompute amortized over 32 elements.

#define NB    4
#define NN    1024
#define NH    32
#define TPB   128                        // 4 warps / block
#define GRID  444                        // 3 blocks/SM * 148 SMs
#define NWT2  (NB * NN * (NN / 32))      // 131072 warp-tiles of 32 j's

static __device__ __forceinline__ uint32_t to_tf32(float x) {
    uint32_t r;
    asm("cvt.rna.tf32.f32 %0, %1;" : "=r"(r) : "f"(x));
    return r;
}

// D += A*B (in-place accumulate)
static __device__ __forceinline__ void mma_acc(float* d, const uint32_t* a,
                                               const uint32_t* b) {
    asm volatile(
        "mma.sync.aligned.m16n8k8.row.col.f32.tf32.tf32.f32 "
        "{%0,%1,%2,%3}, {%4,%5,%6,%7}, {%8,%9}, {%0,%1,%2,%3};"
        : "+f"(d[0]), "+f"(d[1]), "+f"(d[2]), "+f"(d[3])
        : "r"(a[0]), "r"(a[1]), "r"(a[2]), "r"(a[3]), "r"(b[0]), "r"(b[1]));
}
// D = A*B + {c0,c1,c0,c1}  (bias init: writes D fresh)
static __device__ __forceinline__ void mma_bias(float* d, const uint32_t* a,
                                                const uint32_t* b,
                                                float c0, float c1) {
    asm volatile(
        "mma.sync.aligned.m16n8k8.row.col.f32.tf32.tf32.f32 "
        "{%0,%1,%2,%3}, {%4,%5,%6,%7}, {%8,%9}, {%10,%11,%10,%11};"
        : "=f"(d[0]), "=f"(d[1]), "=f"(d[2]), "=f"(d[3])
        : "r"(a[0]), "r"(a[1]), "r"(a[2]), "r"(a[3]), "r"(b[0]), "r"(b[1]),
          "f"(c0), "f"(c1));
}

// softplus(x) = max(x,0) + ln2 * lg2(1 + 2^(-|x|*log2e)), MUFU approx
static __device__ __forceinline__ float softplus_fast(float x) {
    float t, l;
    const float nax = -fabsf(x) * 1.442695041f;
    asm("ex2.approx.f32 %0, %1;" : "=f"(t) : "f"(nax));
    asm("lg2.approx.f32 %0, %1;" : "=f"(l) : "f"(t + 1.0f));
    return fmaxf(x, 0.0f) + 0.693147181f * l;
}

__global__ void __launch_bounds__(TPB)
lf_mma7_kernel(const float* __restrict__ weights,
               const float* __restrict__ distances,
               const float* __restrict__ W1,
               const float* __restrict__ b1,
               const float* __restrict__ W2,
               const float* __restrict__ b2,
               const float* __restrict__ W3,
               const float* __restrict__ b3,
               float* __restrict__ out)
{
    __shared__ float  sW[NB * NN];    // all weights (16 KB)
    __shared__ float4 sW1[NH];        // {W1[0,h], W1[1,h], W1[2,h], b1[h]}
    __shared__ float2 sBW[NH];        // {b2[k], W3[k]}
    __shared__ float  sW2[NH * NH];   // W2[h][n] row-major

    const int tid  = threadIdx.x;
    const int wid  = tid >> 5;
    const int lane = tid & 31;
    const int q    = lane & 3;        // k / col position in quad
    const int g    = lane >> 2;       // row position

    for (int x = tid; x < (NB * NN) / 4; x += TPB)
        ((float4*)sW)[x] = ((const float4*)weights)[x];
    for (int x = tid; x < (NH * NH) / 4; x += TPB)
        ((float4*)sW2)[x] = ((const float4*)W2)[x];
    if (tid < NH) {
        sW1[tid] = make_float4(W1[tid], W1[NH + tid], W1[2 * NH + tid], b1[tid]);
        sBW[tid] = make_float2(b2[tid], W3[tid]);
    }
    __syncthreads();

    // ---- loop-invariant register state ----
    uint32_t bf[4][4][2];             // W2^T fragments (tf32)
#pragma unroll
    for (int kt = 0; kt < 4; kt++)
#pragma unroll
        for (int nt = 0; nt < 4; nt++) {
            bf[kt][nt][0] = to_tf32(sW2[(kt * 8 + q) * NH + nt * 8 + g]);
            bf[kt][nt][1] = to_tf32(sW2[(kt * 8 + q + 4) * NH + nt * 8 + g]);
        }
    float4 w1c[8];                    // W1 cols h = q + {0,4} + 8kt
#pragma unroll
    for (int kt = 0; kt < 4; kt++) {
        w1c[2 * kt]     = sW1[8 * kt + q];
        w1c[2 * kt + 1] = sW1[8 * kt + q + 4];
    }
    float2 bw[8];                     // {b2, W3} at n = 8nt + 2q + {0,1}
#pragma unroll
    for (int nt = 0; nt < 4; nt++) {
        bw[2 * nt]     = sBW[8 * nt + 2 * q];
        bw[2 * nt + 1] = sBW[8 * nt + 2 * q + 1];
    }
    const float b3v = b3[0];

    const int gw     = blockIdx.x * 4 + wid;
    const int stride = GRID * 4;

    // prefetch first tile's distances (flat elem offset = t*32 + g)
    float d0 = 0.f, d1 = 0.f, d2 = 0.f, d3 = 0.f;
    if (gw < NWT2) {
        const unsigned off = ((unsigned)gw << 5) + g;
        d0 = __ldcs(distances + off);
        d1 = __ldcs(distances + off + 8);
        d2 = __ldcs(distances + off + 16);
        d3 = __ldcs(distances + off + 24);
    }

    for (int t = gw; t < NWT2; t += stride) {
        const unsigned off = ((unsigned)t << 5) + g;

        const float wi = sW[t >> 5];
        const unsigned jbase = ((unsigned)(t >> 15) << 10) + ((t & 31) << 5) + g;
        const float wj0 = sW[jbase];
        const float wj1 = sW[jbase + 8];
        const float wj2 = sW[jbase + 16];
        const float wj3 = sW[jbase + 24];

        // ai[h] = wi*W1[0,h] + b1[h] at this thread's cols (shared by A and B)
        float ai[8];
#pragma unroll
        for (int kt = 0; kt < 4; kt++) {
            ai[2 * kt]     = fmaf(w1c[2 * kt].x,     wi, w1c[2 * kt].w);
            ai[2 * kt + 1] = fmaf(w1c[2 * kt + 1].x, wi, w1c[2 * kt + 1].w);
        }

        float accA[4][4], accB[4][4];

        // ---- kt-interleaved: build 8 A-frag values, fire 8 MMAs ----
#pragma unroll
        for (int kt = 0; kt < 4; kt++) {
            const float4 cA = w1c[2 * kt];
            const float4 cB = w1c[2 * kt + 1];
            const float aA = ai[2 * kt];
            const float aB = ai[2 * kt + 1];
            uint32_t afA[4], afB[4];
            afA[0] = __float_as_uint(fmaxf(fmaf(cA.z, d0, fmaf(cA.y, wj0, aA)), 0.f));
            afA[1] = __float_as_uint(fmaxf(fmaf(cA.z, d1, fmaf(cA.y, wj1, aA)), 0.f));
            afA[2] = __float_as_uint(fmaxf(fmaf(cB.z, d0, fmaf(cB.y, wj0, aB)), 0.f));
            afA[3] = __float_as_uint(fmaxf(fmaf(cB.z, d1, fmaf(cB.y, wj1, aB)), 0.f));
            afB[0] = __float_as_uint(fmaxf(fmaf(cA.z, d2, fmaf(cA.y, wj2, aA)), 0.f));
            afB[1] = __float_as_uint(fmaxf(fmaf(cA.z, d3, fmaf(cA.y, wj3, aA)), 0.f));
            afB[2] = __float_as_uint(fmaxf(fmaf(cB.z, d2, fmaf(cB.y, wj2, aB)), 0.f));
            afB[3] = __float_as_uint(fmaxf(fmaf(cB.z, d3, fmaf(cB.y, wj3, aB)), 0.f));

            if (kt == 0) {
#pragma unroll
                for (int nt = 0; nt < 4; nt++) {
                    mma_bias(accA[nt], afA, bf[0][nt], bw[2*nt].x, bw[2*nt+1].x);
                    mma_bias(accB[nt], afB, bf[0][nt], bw[2*nt].x, bw[2*nt+1].x);
                }
            } else {
#pragma unroll
                for (int nt = 0; nt < 4; nt++) {
                    mma_acc(accA[nt], afA, bf[kt][nt]);
                    mma_acc(accB[nt], afB, bf[kt][nt]);
                }
            }
        }

        // prefetch next tile (hide LDG under epilogue)
        const int tn = t + stride;
        float d0n = 0.f, d1n = 0.f, d2n = 0.f, d3n = 0.f;
        if (tn < NWT2) {
            const unsigned offn = ((unsigned)tn << 5) + g;
            d0n = __ldcs(distances + offn);
            d1n = __ldcs(distances + offn + 8);
            d2n = __ldcs(distances + offn + 16);
            d3n = __ldcs(distances + offn + 24);
        }

        // ---- epilogue: relu . W3, quad reduce, softplus ----
        float s0 = 0.f, s1 = 0.f, s2 = 0.f, s3 = 0.f;
#pragma unroll
        for (int nt = 0; nt < 4; nt++) {
            const float w30 = bw[2 * nt].y;
            const float w31 = bw[2 * nt + 1].y;
            s0 = fmaf(fmaxf(accA[nt][0], 0.f), w30, s0);
            s0 = fmaf(fmaxf(accA[nt][1], 0.f), w31, s0);
            s1 = fmaf(fmaxf(accA[nt][2], 0.f), w30, s1);
            s1 = fmaf(fmaxf(accA[nt][3], 0.f), w31, s1);
            s2 = fmaf(fmaxf(accB[nt][0], 0.f), w30, s2);
            s2 = fmaf(fmaxf(accB[nt][1], 0.f), w31, s2);
            s3 = fmaf(fmaxf(accB[nt][2], 0.f), w30, s3);
            s3 = fmaf(fmaxf(accB[nt][3], 0.f), w31, s3);
        }
        s0 += __shfl_xor_sync(0xffffffffu, s0, 1);
        s1 += __shfl_xor_sync(0xffffffffu, s1, 1);
        s2 += __shfl_xor_sync(0xffffffffu, s2, 1);
        s3 += __shfl_xor_sync(0xffffffffu, s3, 1);
        s0 += __shfl_xor_sync(0xffffffffu, s0, 2);
        s1 += __shfl_xor_sync(0xffffffffu, s1, 2);
        s2 += __shfl_xor_sync(0xffffffffu, s2, 2);
        s3 += __shfl_xor_sync(0xffffffffu, s3, 2);

        if (q == 0) {
            __stcs(out + off,      softplus_fast(s0 + b3v));
            __stcs(out + off + 8,  softplus_fast(s1 + b3v));
            __stcs(out + off + 16, softplus_fast(s2 + b3v));
            __stcs(out + off + 24, softplus_fast(s3 + b3v));
        }

        d0 = d0n; d1 = d1n; d2 = d2n; d3 = d3n;
    }
}

extern "C" void kernel_launch(void* const* d_in, const int* in_sizes, int n_in,
                              void* d_out, int out_size)
{
    const float* weights   = (const float*)d_in[0];
    const float* distances = (const float*)d_in[1];
    const float* W1        = (const float*)d_in[2];
    const float* b1        = (const float*)d_in[3];
    const float* W2        = (const float*)d_in[4];
    const float* b2        = (const float*)d_in[5];
    const float* W3        = (const float*)d_in[6];
    const float* b3        = (const float*)d_in[7];
    float* out             = (float*)d_out;

    lf_mma7_kernel<<<GRID, TPB>>>(weights, distances, W1, b1, W2, b2, W3, b3, out);
}